// round 12
// baseline (speedup 1.0000x reference)
#include <cuda_runtime.h>
#include <cstdint>

// Problem constants
#define NN      131072
#define MDIM    64
#define KDIM    8
#define TILE_N  32                  // n's per block
#define MCHUNK  2                   // m's staged per chunk (64B per n per array)
#define NCHUNK  (MDIM / MCHUNK)     // 32
#define NSTRIDE 20                  // 16 data floats + 4 pad (conflict-free, see analysis)
#define THREADS 128                 // 4 threads per n
#define NBLOCKS (NN / TILE_N)       // 4096
#define STAGES  3
#define ARR_FLOATS (TILE_N * NSTRIDE)        // 640
#define BUF_FLOATS (4 * ARR_FLOATS)          // 2560 floats per pipeline stage
#define SMEM_FLOATS (STAGES * BUF_FLOATS)    // 7680 floats = 30720 B (static)

__device__ float g_partials[NBLOCKS];
__device__ unsigned int g_count = 0;      // self-resetting last-block ticket

// ---- f32x2 packed-FMA helpers (FFMA2 is only reachable via PTX) ----
__device__ __forceinline__ unsigned long long pack2(float lo, float hi) {
    unsigned long long r;
    asm("mov.b64 %0, {%1, %2};" : "=l"(r) : "f"(lo), "f"(hi));
    return r;
}
__device__ __forceinline__ unsigned long long ffma2(unsigned long long a,
                                                    unsigned long long b,
                                                    unsigned long long c) {
    unsigned long long d;
    asm("fma.rn.f32x2 %0, %1, %2, %3;" : "=l"(d) : "l"(a), "l"(b), "l"(c));
    return d;
}
__device__ __forceinline__ void unpack2(unsigned long long v, float& lo, float& hi) {
    asm("mov.b64 {%0, %1}, %2;" : "=f"(lo), "=f"(hi) : "l"(v));
}

// ---- cp.async helpers ----
__device__ __forceinline__ void cp_async16(uint32_t saddr, const float* gptr) {
    asm volatile("cp.async.cg.shared.global [%0], [%1], 16;" :: "r"(saddr), "l"(gptr));
}
__device__ __forceinline__ void cp_commit() {
    asm volatile("cp.async.commit_group;");
}
template<int N> __device__ __forceinline__ void cp_wait() {
    asm volatile("cp.async.wait_group %0;" :: "n"(N));
}

__global__ __launch_bounds__(THREADS)
void sumrate_main_kernel(const float* __restrict__ Hr, const float* __restrict__ Hi,
                         const float* __restrict__ Vr, const float* __restrict__ Vi,
                         const float* __restrict__ noise_p, float* __restrict__ out) {
    __shared__ __align__(16) float smem[SMEM_FLOATS];  // [3][4][ARR_FLOATS]
    __shared__ float wred[4];
    __shared__ int slast;

    const int t       = threadIdx.x;
    const int n0      = blockIdx.x * TILE_N;
    const int n_local = t >> 2;     // 0..31
    const int k1h     = t & 3;      // handles k1 = k1h and k1h+4
    const int lane    = t & 31;
    const int wid     = t >> 5;

    // staging map: per chunk per array, 32 n * 4 float4 = 128 float4 over 128 threads (1 each)
    const int snl  = t >> 2;        // n for staging (0..31)
    const int spos = t & 3;         // float4 position within the 16-float chunk row
    const int soff = snl * NSTRIDE + spos * 4;
    const int gbase = (n0 + snl) * (MDIM * KDIM) + spos * 4;

    uint32_t smem_u32;
    asm("{ .reg .u64 a; cvta.to.shared.u64 a, %1; cvt.u32.u64 %0, a; }"
        : "=r"(smem_u32) : "l"(smem));

    auto stage = [&](int c, int buf) {
        const float* pHr = Hr + gbase + c * (MCHUNK * KDIM);
        const float* pHi = Hi + gbase + c * (MCHUNK * KDIM);
        const float* pVr = Vr + gbase + c * (MCHUNK * KDIM);
        const float* pVi = Vi + gbase + c * (MCHUNK * KDIM);
        const uint32_t sb = smem_u32 + (uint32_t)(buf * BUF_FLOATS + soff) * 4u;
        cp_async16(sb + (uint32_t)(0 * ARR_FLOATS) * 4u, pHr);
        cp_async16(sb + (uint32_t)(1 * ARR_FLOATS) * 4u, pHi);
        cp_async16(sb + (uint32_t)(2 * ARR_FLOATS) * 4u, pVr);
        cp_async16(sb + (uint32_t)(3 * ARR_FLOATS) * 4u, pVi);
        cp_commit();
    };

    // accumulators: [j][p] -> k1 = k1h + 4j, k2 pair (2p, 2p+1)
    unsigned long long re2[2][4] = {{0,0,0,0},{0,0,0,0}};
    unsigned long long im2[2][4] = {{0,0,0,0},{0,0,0,0}};

    // prologue: 2 chunks in flight
    stage(0, 0);
    stage(1, 1);

    #pragma unroll 1
    for (int c = 0; c < NCHUNK; ++c) {
        if (c + 1 < NCHUNK) cp_wait<1>();   // chunk c arrived (c+1 still pending)
        else                cp_wait<0>();
        __syncthreads();                    // publish chunk c; orders reuse of buffer (c+2)%3
        if (c + 2 < NCHUNK) stage(c + 2, (c + 2) % STAGES);

        const float* sHr = smem + (c % STAGES) * BUF_FLOATS;
        const float* sHi = sHr + ARR_FLOATS;
        const float* sVr = sHr + 2 * ARR_FLOATS;
        const float* sVi = sHr + 3 * ARR_FLOATS;
        const int base0 = n_local * NSTRIDE;

        #pragma unroll
        for (int m = 0; m < MCHUNK; ++m) {
            const int b = base0 + m * KDIM;
            // H scalars: banks 20*nl + k1h (+4) -> each warp covers 0..31 uniquely
            float hr0 = sHr[b + k1h];
            float hr1 = sHr[b + k1h + 4];
            float hi0 = sHi[b + k1h];
            float hi1 = sHi[b + k1h + 4];
            // V row (broadcast LDS.128 across the 4 threads of this n)
            ulonglong2 vra = *(const ulonglong2*)&sVr[b];
            ulonglong2 vrb = *(const ulonglong2*)&sVr[b + 4];
            ulonglong2 via = *(const ulonglong2*)&sVi[b];
            ulonglong2 vib = *(const ulonglong2*)&sVi[b + 4];

            {   // k1 = k1h
                unsigned long long hr2  = pack2(hr0,  hr0);
                unsigned long long hi2  = pack2(hi0,  hi0);
                unsigned long long nhi2 = pack2(-hi0, -hi0);
                re2[0][0] = ffma2(hr2, vra.x, re2[0][0]); re2[0][0] = ffma2(nhi2, via.x, re2[0][0]);
                im2[0][0] = ffma2(hr2, via.x, im2[0][0]); im2[0][0] = ffma2(hi2,  vra.x, im2[0][0]);
                re2[0][1] = ffma2(hr2, vra.y, re2[0][1]); re2[0][1] = ffma2(nhi2, via.y, re2[0][1]);
                im2[0][1] = ffma2(hr2, via.y, im2[0][1]); im2[0][1] = ffma2(hi2,  vra.y, im2[0][1]);
                re2[0][2] = ffma2(hr2, vrb.x, re2[0][2]); re2[0][2] = ffma2(nhi2, vib.x, re2[0][2]);
                im2[0][2] = ffma2(hr2, vib.x, im2[0][2]); im2[0][2] = ffma2(hi2,  vrb.x, im2[0][2]);
                re2[0][3] = ffma2(hr2, vrb.y, re2[0][3]); re2[0][3] = ffma2(nhi2, vib.y, re2[0][3]);
                im2[0][3] = ffma2(hr2, vib.y, im2[0][3]); im2[0][3] = ffma2(hi2,  vrb.y, im2[0][3]);
            }
            {   // k1 = k1h + 4
                unsigned long long hr2  = pack2(hr1,  hr1);
                unsigned long long hi2  = pack2(hi1,  hi1);
                unsigned long long nhi2 = pack2(-hi1, -hi1);
                re2[1][0] = ffma2(hr2, vra.x, re2[1][0]); re2[1][0] = ffma2(nhi2, via.x, re2[1][0]);
                im2[1][0] = ffma2(hr2, via.x, im2[1][0]); im2[1][0] = ffma2(hi2,  vra.x, im2[1][0]);
                re2[1][1] = ffma2(hr2, vra.y, re2[1][1]); re2[1][1] = ffma2(nhi2, via.y, re2[1][1]);
                im2[1][1] = ffma2(hr2, via.y, im2[1][1]); im2[1][1] = ffma2(hi2,  vra.y, im2[1][1]);
                re2[1][2] = ffma2(hr2, vrb.x, re2[1][2]); re2[1][2] = ffma2(nhi2, vib.x, re2[1][2]);
                im2[1][2] = ffma2(hr2, vib.x, im2[1][2]); im2[1][2] = ffma2(hi2,  vrb.x, im2[1][2]);
                re2[1][3] = ffma2(hr2, vrb.y, re2[1][3]); re2[1][3] = ffma2(nhi2, vib.y, re2[1][3]);
                im2[1][3] = ffma2(hr2, vib.y, im2[1][3]); im2[1][3] = ffma2(hi2,  vrb.y, im2[1][3]);
            }
        }
    }

    // ---- epilogue: SINR + rate for the thread's two k1 values ----
    const float noise = __ldg(noise_p);
    float rate = 0.0f;
    #pragma unroll
    for (int j = 0; j < 2; ++j) {
        float ref[8], imf[8];
        #pragma unroll
        for (int p = 0; p < 4; ++p) {
            unpack2(re2[j][p], ref[2 * p], ref[2 * p + 1]);
            unpack2(im2[j][p], imf[2 * p], imf[2 * p + 1]);
        }
        const int myk1 = k1h + 4 * j;
        float ssum = 0.0f, nom = 0.0f;
        #pragma unroll
        for (int k2 = 0; k2 < 8; ++k2) {
            float nr = ref[k2] * ref[k2] + imf[k2] * imf[k2];
            ssum += nr;
            if (k2 == myk1) nom = nr;   // SEL, no dynamic indexing
        }
        const float denom = ssum - nom + noise;
        rate += log2f(1.0f + nom / denom);
    }

    // ---- deterministic block reduction (warp shuffles + 4-way combine) ----
    #pragma unroll
    for (int off = 16; off > 0; off >>= 1)
        rate += __shfl_down_sync(0xffffffffu, rate, off);
    if (lane == 0) wred[wid] = rate;
    __syncthreads();

    if (t == 0) {
        float bsum = wred[0] + wred[1] + wred[2] + wred[3];
        g_partials[blockIdx.x] = bsum;
        __threadfence();
        unsigned int ticket = atomicAdd(&g_count, 1u);
        slast = (ticket == (unsigned int)(NBLOCKS - 1));
    }
    __syncthreads();

    // ---- last block performs the fixed-order final reduction ----
    if (slast) {
        __threadfence();  // ensure all partials visible
        float s = 0.0f;
        for (int i = t; i < NBLOCKS; i += THREADS) s += g_partials[i];
        #pragma unroll
        for (int off = 16; off > 0; off >>= 1)
            s += __shfl_down_sync(0xffffffffu, s, off);
        if (lane == 0) wred[wid] = s;
        __syncthreads();
        if (t == 0) {
            float total = wred[0] + wred[1] + wred[2] + wred[3];
            out[0] = -total / (float)NN;   // loss = -mean over n of sum_k rate
            g_count = 0;                   // reset for next graph replay
        }
    }
}

extern "C" void kernel_launch(void* const* d_in, const int* in_sizes, int n_in,
                              void* d_out, int out_size) {
    const float* Hr  = (const float*)d_in[0];
    const float* Hi  = (const float*)d_in[1];
    const float* Vr  = (const float*)d_in[2];
    const float* Vi  = (const float*)d_in[3];
    const float* np_ = (const float*)d_in[4];
    float* out = (float*)d_out;

    sumrate_main_kernel<<<NBLOCKS, THREADS>>>(Hr, Hi, Vr, Vi, np_, out);
}

// round 13
// speedup vs baseline: 1.1009x; 1.1009x over previous
#include <cuda_runtime.h>
#include <cstdint>

// Problem constants
#define NN      131072
#define MDIM    64
#define KDIM    8
#define TILE_N  32                  // n's per block
#define MCHUNK  4                   // m's staged per chunk
#define NCHUNK  (MDIM / MCHUNK)     // 16
#define NSTRIDE 36                  // 32 data floats + 4 pad (36 % 32 == 4 -> conflict-free)
#define THREADS 128                 // 4 threads per n
#define NBLOCKS (NN / TILE_N)       // 4096
#define ARR_FLOATS (TILE_N * NSTRIDE)     // 1152
#define BUF_FLOATS (4 * ARR_FLOATS)       // 4608 floats per pipeline stage
#define SMEM_BYTES (2 * BUF_FLOATS * 4)   // 36864 B (double-buffered)

__device__ float g_partials[NBLOCKS];
__device__ unsigned int g_count = 0;      // self-resetting ticket counter

// ---- f32x2 packed-FMA helpers (FFMA2 is only reachable via PTX) ----
__device__ __forceinline__ unsigned long long pack2(float lo, float hi) {
    unsigned long long r;
    asm("mov.b64 %0, {%1, %2};" : "=l"(r) : "f"(lo), "f"(hi));
    return r;
}
__device__ __forceinline__ unsigned long long ffma2(unsigned long long a,
                                                    unsigned long long b,
                                                    unsigned long long c) {
    unsigned long long d;
    asm("fma.rn.f32x2 %0, %1, %2, %3;" : "=l"(d) : "l"(a), "l"(b), "l"(c));
    return d;
}
__device__ __forceinline__ void unpack2(unsigned long long v, float& lo, float& hi) {
    asm("mov.b64 {%0, %1}, %2;" : "=f"(lo), "=f"(hi) : "l"(v));
}

// ---- cp.async helpers (with L2 256B prefetch hint: coarser DRAM request stream) ----
__device__ __forceinline__ void cp_async16(uint32_t saddr, const float* gptr) {
    asm volatile("cp.async.cg.shared.global.L2::256B [%0], [%1], 16;"
                 :: "r"(saddr), "l"(gptr));
}
__device__ __forceinline__ void cp_commit() {
    asm volatile("cp.async.commit_group;");
}
template<int N> __device__ __forceinline__ void cp_wait() {
    asm volatile("cp.async.wait_group %0;" :: "n"(N));
}

__global__ __launch_bounds__(THREADS)
void sumrate_main_kernel(const float* __restrict__ Hr, const float* __restrict__ Hi,
                         const float* __restrict__ Vr, const float* __restrict__ Vi,
                         const float* __restrict__ noise_p, float* __restrict__ out) {
    extern __shared__ __align__(16) float smem[];  // [2][4][ARR_FLOATS]
    __shared__ float wred[4];
    __shared__ int slast;

    const int t       = threadIdx.x;
    const int n0      = blockIdx.x * TILE_N;
    const int n_local = t >> 2;     // 0..31
    const int k1h     = t & 3;      // handles k1 = k1h and k1h+4
    const int lane    = t & 31;
    const int wid     = t >> 5;

    // staging map: per chunk per array, 32 n * 8 float4 = 256 float4 over 128 threads (2 each)
    int goff0, goff1, soff0, soff1;
    {
        const int idx0 = t, idx1 = t + THREADS;
        const int nl0 = idx0 >> 3, pos0 = idx0 & 7;
        const int nl1 = idx1 >> 3, pos1 = idx1 & 7;
        goff0 = (n0 + nl0) * (MDIM * KDIM) + pos0 * 4;
        goff1 = (n0 + nl1) * (MDIM * KDIM) + pos1 * 4;
        soff0 = nl0 * NSTRIDE + pos0 * 4;
        soff1 = nl1 * NSTRIDE + pos1 * 4;
    }
    // hoisted per-array base pointers (less per-chunk ALU)
    const float* pHr0 = Hr + goff0;  const float* pHr1 = Hr + goff1;
    const float* pHi0 = Hi + goff0;  const float* pHi1 = Hi + goff1;
    const float* pVr0 = Vr + goff0;  const float* pVr1 = Vr + goff1;
    const float* pVi0 = Vi + goff0;  const float* pVi1 = Vi + goff1;

    uint32_t smem_u32;
    asm("{ .reg .u64 a; cvta.to.shared.u64 a, %1; cvt.u32.u64 %0, a; }"
        : "=r"(smem_u32) : "l"(smem));

    auto stage = [&](int c, int buf) {
        const int g = c * (MCHUNK * KDIM);
        const uint32_t sb = smem_u32 + (uint32_t)(buf * BUF_FLOATS) * 4u;
        cp_async16(sb + (uint32_t)(0 * ARR_FLOATS + soff0) * 4u, pHr0 + g);
        cp_async16(sb + (uint32_t)(0 * ARR_FLOATS + soff1) * 4u, pHr1 + g);
        cp_async16(sb + (uint32_t)(1 * ARR_FLOATS + soff0) * 4u, pHi0 + g);
        cp_async16(sb + (uint32_t)(1 * ARR_FLOATS + soff1) * 4u, pHi1 + g);
        cp_async16(sb + (uint32_t)(2 * ARR_FLOATS + soff0) * 4u, pVr0 + g);
        cp_async16(sb + (uint32_t)(2 * ARR_FLOATS + soff1) * 4u, pVr1 + g);
        cp_async16(sb + (uint32_t)(3 * ARR_FLOATS + soff0) * 4u, pVi0 + g);
        cp_async16(sb + (uint32_t)(3 * ARR_FLOATS + soff1) * 4u, pVi1 + g);
    };

    // accumulators: [j][p] -> k1 = k1h + 4j, k2 pair (2p, 2p+1)
    unsigned long long re2[2][4] = {{0,0,0,0},{0,0,0,0}};
    unsigned long long im2[2][4] = {{0,0,0,0},{0,0,0,0}};

    // prologue: prefetch chunk 0
    stage(0, 0); cp_commit();

    #pragma unroll 1
    for (int c = 0; c < NCHUNK; ++c) {
        if (c + 1 < NCHUNK) {
            stage(c + 1, (c + 1) & 1);   // prefetch next chunk into other buffer
            cp_commit();
            cp_wait<1>();                // chunk c complete (1 group still pending)
        } else {
            cp_wait<0>();
        }
        __syncthreads();                 // all threads' copies for chunk c visible

        const float* sHr = smem + (c & 1) * BUF_FLOATS;
        const float* sHi = sHr + ARR_FLOATS;
        const float* sVr = sHr + 2 * ARR_FLOATS;
        const float* sVi = sHr + 3 * ARR_FLOATS;
        const int base0 = n_local * NSTRIDE;

        #pragma unroll
        for (int m = 0; m < MCHUNK; ++m) {
            const int b = base0 + m * KDIM;
            // H scalars: stride-4 across k1h -> conflict-free
            float hr0 = sHr[b + k1h];
            float hr1 = sHr[b + k1h + 4];
            float hi0 = sHi[b + k1h];
            float hi1 = sHi[b + k1h + 4];
            // V row (broadcast LDS.128 across the 4 threads of this n)
            ulonglong2 vra = *(const ulonglong2*)&sVr[b];
            ulonglong2 vrb = *(const ulonglong2*)&sVr[b + 4];
            ulonglong2 via = *(const ulonglong2*)&sVi[b];
            ulonglong2 vib = *(const ulonglong2*)&sVi[b + 4];

            {   // k1 = k1h
                unsigned long long hr2  = pack2(hr0,  hr0);
                unsigned long long hi2  = pack2(hi0,  hi0);
                unsigned long long nhi2 = pack2(-hi0, -hi0);
                re2[0][0] = ffma2(hr2, vra.x, re2[0][0]); re2[0][0] = ffma2(nhi2, via.x, re2[0][0]);
                im2[0][0] = ffma2(hr2, via.x, im2[0][0]); im2[0][0] = ffma2(hi2,  vra.x, im2[0][0]);
                re2[0][1] = ffma2(hr2, vra.y, re2[0][1]); re2[0][1] = ffma2(nhi2, via.y, re2[0][1]);
                im2[0][1] = ffma2(hr2, via.y, im2[0][1]); im2[0][1] = ffma2(hi2,  vra.y, im2[0][1]);
                re2[0][2] = ffma2(hr2, vrb.x, re2[0][2]); re2[0][2] = ffma2(nhi2, vib.x, re2[0][2]);
                im2[0][2] = ffma2(hr2, vib.x, im2[0][2]); im2[0][2] = ffma2(hi2,  vrb.x, im2[0][2]);
                re2[0][3] = ffma2(hr2, vrb.y, re2[0][3]); re2[0][3] = ffma2(nhi2, vib.y, re2[0][3]);
                im2[0][3] = ffma2(hr2, vib.y, im2[0][3]); im2[0][3] = ffma2(hi2,  vrb.y, im2[0][3]);
            }
            {   // k1 = k1h + 4
                unsigned long long hr2  = pack2(hr1,  hr1);
                unsigned long long hi2  = pack2(hi1,  hi1);
                unsigned long long nhi2 = pack2(-hi1, -hi1);
                re2[1][0] = ffma2(hr2, vra.x, re2[1][0]); re2[1][0] = ffma2(nhi2, via.x, re2[1][0]);
                im2[1][0] = ffma2(hr2, via.x, im2[1][0]); im2[1][0] = ffma2(hi2,  vra.x, im2[1][0]);
                re2[1][1] = ffma2(hr2, vra.y, re2[1][1]); re2[1][1] = ffma2(nhi2, via.y, re2[1][1]);
                im2[1][1] = ffma2(hr2, via.y, im2[1][1]); im2[1][1] = ffma2(hi2,  vra.y, im2[1][1]);
                re2[1][2] = ffma2(hr2, vrb.x, re2[1][2]); re2[1][2] = ffma2(nhi2, vib.x, re2[1][2]);
                im2[1][2] = ffma2(hr2, vib.x, im2[1][2]); im2[1][2] = ffma2(hi2,  vrb.x, im2[1][2]);
                re2[1][3] = ffma2(hr2, vrb.y, re2[1][3]); re2[1][3] = ffma2(nhi2, vib.y, re2[1][3]);
                im2[1][3] = ffma2(hr2, vib.y, im2[1][3]); im2[1][3] = ffma2(hi2,  vrb.y, im2[1][3]);
            }
        }
        __syncthreads();   // protect this buffer before it is re-staged at c+2
    }

    // ---- epilogue: SINR + rate for the thread's two k1 values ----
    const float noise = __ldg(noise_p);
    float rate = 0.0f;
    #pragma unroll
    for (int j = 0; j < 2; ++j) {
        float ref[8], imf[8];
        #pragma unroll
        for (int p = 0; p < 4; ++p) {
            unpack2(re2[j][p], ref[2 * p], ref[2 * p + 1]);
            unpack2(im2[j][p], imf[2 * p], imf[2 * p + 1]);
        }
        const int myk1 = k1h + 4 * j;
        float ssum = 0.0f, nom = 0.0f;
        #pragma unroll
        for (int k2 = 0; k2 < 8; ++k2) {
            float nr = ref[k2] * ref[k2] + imf[k2] * imf[k2];
            ssum += nr;
            if (k2 == myk1) nom = nr;   // SEL, no dynamic indexing
        }
        const float denom = ssum - nom + noise;
        rate += log2f(1.0f + nom / denom);
    }

    // ---- deterministic block reduction (warp shuffles + 4-way combine) ----
    #pragma unroll
    for (int off = 16; off > 0; off >>= 1)
        rate += __shfl_down_sync(0xffffffffu, rate, off);
    if (lane == 0) wred[wid] = rate;
    __syncthreads();

    if (t == 0) {
        float bsum = wred[0] + wred[1] + wred[2] + wred[3];
        g_partials[blockIdx.x] = bsum;
        __threadfence();
        unsigned int ticket = atomicAdd(&g_count, 1u);
        slast = (ticket == (unsigned int)(NBLOCKS - 1));
    }
    __syncthreads();

    // ---- last block performs the fixed-order final reduction ----
    if (slast) {
        __threadfence();  // ensure all partials visible
        float s = 0.0f;
        for (int i = t; i < NBLOCKS; i += THREADS) s += g_partials[i];
        #pragma unroll
        for (int off = 16; off > 0; off >>= 1)
            s += __shfl_down_sync(0xffffffffu, s, off);
        if (lane == 0) wred[wid] = s;
        __syncthreads();
        if (t == 0) {
            float total = wred[0] + wred[1] + wred[2] + wred[3];
            out[0] = -total / (float)NN;   // loss = -mean over n of sum_k rate
            g_count = 0;                   // reset for next graph replay
        }
    }
}

extern "C" void kernel_launch(void* const* d_in, const int* in_sizes, int n_in,
                              void* d_out, int out_size) {
    const float* Hr  = (const float*)d_in[0];
    const float* Hi  = (const float*)d_in[1];
    const float* Vr  = (const float*)d_in[2];
    const float* Vi  = (const float*)d_in[3];
    const float* np_ = (const float*)d_in[4];
    float* out = (float*)d_out;

    sumrate_main_kernel<<<NBLOCKS, THREADS, SMEM_BYTES>>>(Hr, Hi, Vr, Vi, np_, out);
}